// round 14
// baseline (speedup 1.0000x reference)
#include <cuda_runtime.h>
#include <cuda_fp16.h>
#include <cstdint>
#include <cstddef>

// ---------------------------------------------------------------------------
// Problem dims
// ---------------------------------------------------------------------------
constexpr int kB  = 4096;   // batch
constexpr int kIN = 1024;   // input dim
constexpr int kV  = 48;     // vocab (num MLPs)
constexpr int kH  = 512;    // hidden
constexpr int kO  = 64;     // out per MLP

// ---------------------------------------------------------------------------
// Device scratch: fp16 operands + intermediates
// ---------------------------------------------------------------------------
__device__ __align__(1024) __half g_X  [(size_t)kB * kIN];
__device__ __align__(1024) __half g_W1 [(size_t)kV * kH * kIN];  // [v][h][i]
__device__ __align__(1024) __half g_W2 [(size_t)kV * kH * kH];   // [v][k][h]
__device__ __align__(1024) __half g_W3 [(size_t)kV * kO * kH];   // [v][o][k]
__device__ __align__(1024) __half g_H1 [(size_t)kV * kB * kH];   // [v][m][h]
__device__ __align__(1024) __half g_H2 [(size_t)kV * kB * kH];

// ---------------------------------------------------------------------------
// PTX helpers — baseline (non-'a') PTX only: cp.async / ldmatrix / mma.sync
// ---------------------------------------------------------------------------
#define DINLINE __device__ __forceinline__

DINLINE uint32_t smem_u32(const void* p) {
    uint32_t a;
    asm("{ .reg .u64 t; cvta.to.shared.u64 t, %1; cvt.u32.u64 %0, t; }" : "=r"(a) : "l"(p));
    return a;
}
DINLINE uint32_t swz(uint32_t o) { return o ^ ((o >> 3) & 0x70); }

DINLINE void cp16(uint32_t dst, const void* src) {
    asm volatile("cp.async.cg.shared.global [%0], [%1], 16;" :: "r"(dst), "l"(src));
}
DINLINE void cp_commit() { asm volatile("cp.async.commit_group;" ::: "memory"); }
template <int N> DINLINE void cp_wait() {
    asm volatile("cp.async.wait_group %0;" :: "n"(N) : "memory");
}

DINLINE void ldsm4(uint32_t& r0, uint32_t& r1, uint32_t& r2, uint32_t& r3, uint32_t a) {
    asm volatile("ldmatrix.sync.aligned.m8n8.x4.shared.b16 {%0,%1,%2,%3}, [%4];"
                 : "=r"(r0), "=r"(r1), "=r"(r2), "=r"(r3) : "r"(a));
}

DINLINE void mma16816(float* d, const uint32_t* a, const uint32_t* b) {
    asm volatile(
        "mma.sync.aligned.m16n8k16.row.col.f32.f16.f16.f32 "
        "{%0,%1,%2,%3}, {%4,%5,%6,%7}, {%8,%9}, {%0,%1,%2,%3};"
        : "+f"(d[0]), "+f"(d[1]), "+f"(d[2]), "+f"(d[3])
        : "r"(a[0]), "r"(a[1]), "r"(a[2]), "r"(a[3]), "r"(b[0]), "r"(b[1]));
}

// ---------------------------------------------------------------------------
// Prep: fp32 -> fp16 convert of x
// ---------------------------------------------------------------------------
__global__ void convert_x_kernel(const float* __restrict__ x,
                                 __half* __restrict__ o) {
    size_t i = ((size_t)blockIdx.x * 256 + threadIdx.x) * 4;
    float4 f = *reinterpret_cast<const float4*>(x + i);
    __half2 h0 = __floats2half2_rn(f.x, f.y);
    __half2 h1 = __floats2half2_rn(f.z, f.w);
    *reinterpret_cast<uint2*>(o + i) =
        make_uint2(*reinterpret_cast<uint32_t*>(&h0), *reinterpret_cast<uint32_t*>(&h1));
}

// ---------------------------------------------------------------------------
// Prep: per-v transpose [v][R][C] -> [v][C][R] + fp16 convert
// ---------------------------------------------------------------------------
__global__ void transpose_convert_kernel(const float* __restrict__ in,
                                         __half* __restrict__ o,
                                         int R, int C) {
    __shared__ float t[32][33];
    const int v = blockIdx.z;
    const float* src = in + (size_t)v * R * C;
    const size_t ob = (size_t)v * R * C;
    const int tx = threadIdx.x, ty = threadIdx.y;
    const int c = blockIdx.x * 32 + tx;
#pragma unroll
    for (int j = 0; j < 32; j += 8) {
        int r = blockIdx.y * 32 + ty + j;
        t[ty + j][tx] = src[(size_t)r * C + c];
    }
    __syncthreads();
    const int r2 = blockIdx.y * 32 + tx;  // output fast dim (R index)
#pragma unroll
    for (int j = 0; j < 32; j += 8) {
        int c2 = blockIdx.x * 32 + ty + j;  // output row (C index)
        o[ob + (size_t)c2 * R + r2] = __float2half_rn(t[tx][ty + j]);
    }
}

// ---------------------------------------------------------------------------
// Batched fp16 GEMM via mma.sync (fp32 accumulate):
//   D[128 x NT] = A[128 x K] * B[NT x K]^T  (per (m-block, v, n-block) CTA)
//   8 warps, warp grid WG_M x WG_N, warp tile (WM*16) x (WN*8)
//   Kc = 64 per chunk, 3-stage cp.async pipeline, SW128 swizzle, ldmatrix
//   Precomputed loader addresses + double-buffered fragment pipeline.
// ---------------------------------------------------------------------------
template <int NT, int WG_M, int WG_N, int WM, int WN, bool RELU>
__global__ void __launch_bounds__(256) gemm_kernel(
    const __half* __restrict__ A, long long aVStride,
    const __half* __restrict__ B,
    int K, int Ndim, int nPerV,
    const float* __restrict__ bias,
    __half* __restrict__ O,
    float* __restrict__ out)
{
    static_assert(WG_M * WG_N == 8, "8 warps");
    static_assert(WG_M * WM * 16 == 128, "M tile 128");
    static_assert(WG_N * WN * 8 == NT, "N tile");
    static_assert(WN % 2 == 0, "B ldmatrix pairs");

    extern __shared__ __align__(1024) char smem[];
    const uint32_t sb = smem_u32(smem);
    const int tid = threadIdx.x, wid = tid >> 5, lane = tid & 31;
    const int v  = blockIdx.y / nPerV, nb = blockIdx.y % nPerV;
    const int m0 = blockIdx.x * 128;
    const int n0 = nb * NT;
    const int NC = K >> 6;                 // K chunks of 64

    constexpr int A_SZ = 128 * 128;        // bytes per A tile per stage (16KB)
    constexpr int B_SZ = NT * 128;
    constexpr int STG  = A_SZ + B_SZ;
    const uint32_t st[3] = { sb, sb + STG, sb + 2 * STG };

    // ---- precomputed loader slices ----
    // A: 128 rows x 8 16B-units; 2 threads/row, 4 units each
    const int ar  = tid >> 1;
    const int au0 = (tid & 1) * 4;
    uint32_t aOff[4];
#pragma unroll
    for (int u = 0; u < 4; u++) aOff[u] = swz((uint32_t)(ar * 128 + (au0 + u) * 16));
    // B: NT rows x 8 units; BU = NT/32 units per thread
    constexpr int BU  = NT / 32;           // 4 (NT=128) or 2 (NT=64)
    constexpr int TPR = 8 / BU;            // threads per row
    const int br  = tid / TPR;
    const int bu0 = (tid % TPR) * BU;
    uint32_t bOff[BU];
#pragma unroll
    for (int u = 0; u < BU; u++) bOff[u] = swz((uint32_t)(br * 128 + (bu0 + u) * 16));

    const __half* aSrc = A + (size_t)v * aVStride + (size_t)(m0 + ar) * K + au0 * 8;
    const __half* bSrc = B + ((size_t)v * Ndim + n0 + br) * K + bu0 * 8;

    auto load_chunk = [&](int s) {
        const uint32_t aS = st[s], bS = st[s] + A_SZ;
#pragma unroll
        for (int u = 0; u < 4; u++) cp16(aS + aOff[u], aSrc + u * 8);
#pragma unroll
        for (int u = 0; u < BU; u++) cp16(bS + bOff[u], bSrc + u * 8);
        cp_commit();
        aSrc += 64;  // next K chunk
        bSrc += 64;
    };

    // warp tile origin
    const int wm = (wid / WG_N) * (WM * 16);
    const int wn = (wid % WG_N) * (WN * 8);

    float d[WM][WN][4];
#pragma unroll
    for (int i = 0; i < WM; i++)
#pragma unroll
        for (int j = 0; j < WN; j++)
#pragma unroll
            for (int q = 0; q < 4; q++) d[i][j][q] = 0.0f;

    load_chunk(0);
    load_chunk(1);

    // ldmatrix lane patterns: precompute the 4 per-k-step swizzled addrs (k0-dependent part
    // toggles only bits XORed by swizzle; compute fresh per ks but from precomputed row bases)
    const int aRow = (lane & 15);
    const int aKh  = (lane >> 4) * 8;
    const int bRow = (lane & 7) + (((lane >> 4) & 1) << 3);
    const int bKh  = ((lane >> 3) & 1) * 8;

    // fragment double buffers
    uint32_t af[2][WM][4], bf[2][WN][2];

    auto load_frags = [&](uint32_t aS, uint32_t bS, int ks, int buf) {
        const int k0 = ks * 16;
#pragma unroll
        for (int i = 0; i < WM; i++) {
            uint32_t off = swz((uint32_t)((wm + aRow + i * 16) * 128 + (k0 + aKh) * 2));
            ldsm4(af[buf][i][0], af[buf][i][1], af[buf][i][2], af[buf][i][3], aS + off);
        }
#pragma unroll
        for (int j2 = 0; j2 < WN / 2; j2++) {
            uint32_t off = swz((uint32_t)((wn + bRow + j2 * 16) * 128 + (k0 + bKh) * 2));
            ldsm4(bf[buf][2 * j2][0], bf[buf][2 * j2][1],
                  bf[buf][2 * j2 + 1][0], bf[buf][2 * j2 + 1][1], bS + off);
        }
    };

    for (int kc = 0; kc < NC; kc++) {
        const int s = kc % 3;
        if (kc + 2 <= NC) { cp_wait<1>(); } else { cp_wait<0>(); }
        __syncthreads();
        if (kc + 2 < NC) load_chunk((kc + 2) % 3);

        const uint32_t aS = st[s], bS = st[s] + A_SZ;

        load_frags(aS, bS, 0, 0);
#pragma unroll
        for (int ks = 0; ks < 4; ks++) {
            const int cur = ks & 1;
            if (ks < 3) load_frags(aS, bS, ks + 1, cur ^ 1);
#pragma unroll
            for (int i = 0; i < WM; i++)
#pragma unroll
                for (int j = 0; j < WN; j++) mma16816(d[i][j], af[cur][i], bf[cur][j]);
        }
    }

    // ---- epilogue (register fragments, canonical m16n8 D mapping) ----
    const int rBase = lane >> 2;         // 0..7
    const int cBase = (lane & 3) * 2;    // 0,2,4,6
#pragma unroll
    for (int j = 0; j < WN; j++) {
        const int n = n0 + wn + j * 8 + cBase;   // global n (even)
        float bv0 = 0.0f, bv1 = 0.0f;
        if (RELU) {
            bv0 = bias[(size_t)v * kH + n];
            bv1 = bias[(size_t)v * kH + n + 1];
        }
#pragma unroll
        for (int i = 0; i < WM; i++) {
#pragma unroll
            for (int half = 0; half < 2; half++) {
                const int m = m0 + wm + i * 16 + rBase + half * 8;
                float f0 = d[i][j][2 * half];
                float f1 = d[i][j][2 * half + 1];
                if (RELU) {
                    f0 = fmaxf(f0 + bv0, 0.0f);
                    f1 = fmaxf(f1 + bv1, 0.0f);
                    __half2 h2 = __floats2half2_rn(f0, f1);
                    size_t dst = ((size_t)v * kB + m) * kH + n;
                    *reinterpret_cast<uint32_t*>(O + dst) = *reinterpret_cast<uint32_t*>(&h2);
                } else {
                    size_t dst = (size_t)m * ((size_t)kV * kO) + (size_t)v * kO + n;
                    *reinterpret_cast<float2*>(out + dst) = make_float2(f0, f1);
                }
            }
        }
    }
}

// ---------------------------------------------------------------------------
// Launch
// ---------------------------------------------------------------------------
extern "C" void kernel_launch(void* const* d_in, const int* in_sizes, int n_in,
                              void* d_out, int out_size) {
    const float* x  = (const float*)d_in[0];
    const float* W1 = (const float*)d_in[1];
    const float* b1 = (const float*)d_in[2];
    const float* W2 = (const float*)d_in[3];
    const float* b2 = (const float*)d_in[4];
    const float* W3 = (const float*)d_in[5];
    float* out = (float*)d_out;

    void *pX, *pW1, *pW2, *pW3, *pH1, *pH2;
    cudaGetSymbolAddress(&pX,  g_X);
    cudaGetSymbolAddress(&pW1, g_W1);
    cudaGetSymbolAddress(&pW2, g_W2);
    cudaGetSymbolAddress(&pW3, g_W3);
    cudaGetSymbolAddress(&pH1, g_H1);
    cudaGetSymbolAddress(&pH2, g_H2);

    // smem: 3 stages * (16KB A + NT*128 B)
    constexpr int SMEM_BIG = 3 * (128 * 128 + 128 * 128);  // NT=128 -> 96KB
    constexpr int SMEM_SM  = 3 * (128 * 128 + 64 * 128);   // NT=64  -> 72KB
    cudaFuncSetAttribute((const void*)gemm_kernel<128, 2, 4, 4, 4, true>,
                         cudaFuncAttributeMaxDynamicSharedMemorySize, SMEM_BIG);
    cudaFuncSetAttribute((const void*)gemm_kernel<64, 4, 2, 2, 4, false>,
                         cudaFuncAttributeMaxDynamicSharedMemorySize, SMEM_SM);

    // prep: convert x, transpose+convert weights
    convert_x_kernel<<<(kB * kIN) / 1024, 256>>>(x, (__half*)pX);
    dim3 tb(32, 8);
    transpose_convert_kernel<<<dim3(kH / 32, kIN / 32, kV), tb>>>(W1, (__half*)pW1, kIN, kH);
    transpose_convert_kernel<<<dim3(kH / 32, kH / 32, kV), tb>>>(W2, (__half*)pW2, kH, kH);
    transpose_convert_kernel<<<dim3(kO / 32, kH / 32, kV), tb>>>(W3, (__half*)pW3, kH, kO);

    // layer 1: [4096,1024] x [48,512,1024]^T -> H1
    gemm_kernel<128, 2, 4, 4, 4, true><<<dim3(kB / 128, kV * (kH / 128)), 256, SMEM_BIG>>>(
        (const __half*)pX, 0LL, (const __half*)pW1,
        kIN, kH, kH / 128, b1, (__half*)pH1, nullptr);

    // layer 2: H1 x [48,512,512]^T -> H2
    gemm_kernel<128, 2, 4, 4, 4, true><<<dim3(kB / 128, kV * (kH / 128)), 256, SMEM_BIG>>>(
        (const __half*)pH1, (long long)kB * kH, (const __half*)pW2,
        kH, kH, kH / 128, b2, (__half*)pH2, nullptr);

    // layer 3: H2 x [48,64,512]^T -> out (fp32, no bias/relu)
    gemm_kernel<64, 4, 2, 2, 4, false><<<dim3(kB / 128, kV), 256, SMEM_SM>>>(
        (const __half*)pH2, (long long)kB * kH, (const __half*)pW3,
        kH, kO, 1, nullptr, nullptr, out);
}

// round 15
// speedup vs baseline: 1.6459x; 1.6459x over previous
#include <cuda_runtime.h>
#include <cuda_fp16.h>
#include <cstdint>
#include <cstddef>

// ---------------------------------------------------------------------------
// Problem dims
// ---------------------------------------------------------------------------
constexpr int kB  = 4096;   // batch
constexpr int kIN = 1024;   // input dim
constexpr int kV  = 48;     // vocab (num MLPs)
constexpr int kH  = 512;    // hidden
constexpr int kO  = 64;     // out per MLP

// ---------------------------------------------------------------------------
// Device scratch: fp16 operands + intermediates
// ---------------------------------------------------------------------------
__device__ __align__(1024) __half g_X  [(size_t)kB * kIN];
__device__ __align__(1024) __half g_W1 [(size_t)kV * kH * kIN];  // [v][h][i]
__device__ __align__(1024) __half g_W2 [(size_t)kV * kH * kH];   // [v][k][h]
__device__ __align__(1024) __half g_W3 [(size_t)kV * kO * kH];   // [v][o][k]
__device__ __align__(1024) __half g_H1 [(size_t)kV * kB * kH];   // [v][m][h]
__device__ __align__(1024) __half g_H2 [(size_t)kV * kB * kH];

// ---------------------------------------------------------------------------
// PTX helpers — baseline (non-'a') PTX only: cp.async / ldmatrix / mma.sync
// ---------------------------------------------------------------------------
#define DINLINE __device__ __forceinline__

DINLINE uint32_t smem_u32(const void* p) {
    uint32_t a;
    asm("{ .reg .u64 t; cvta.to.shared.u64 t, %1; cvt.u32.u64 %0, t; }" : "=r"(a) : "l"(p));
    return a;
}
DINLINE uint32_t swz(uint32_t o) { return o ^ ((o >> 3) & 0x70); }

DINLINE void cp16(uint32_t dst, const void* src) {
    asm volatile("cp.async.cg.shared.global [%0], [%1], 16;" :: "r"(dst), "l"(src));
}
DINLINE void cp_commit() { asm volatile("cp.async.commit_group;" ::: "memory"); }
template <int N> DINLINE void cp_wait() {
    asm volatile("cp.async.wait_group %0;" :: "n"(N) : "memory");
}

DINLINE void ldsm4(uint32_t& r0, uint32_t& r1, uint32_t& r2, uint32_t& r3, uint32_t a) {
    asm volatile("ldmatrix.sync.aligned.m8n8.x4.shared.b16 {%0,%1,%2,%3}, [%4];"
                 : "=r"(r0), "=r"(r1), "=r"(r2), "=r"(r3) : "r"(a));
}

DINLINE void mma16816(float* d, const uint32_t* a, const uint32_t* b) {
    asm volatile(
        "mma.sync.aligned.m16n8k16.row.col.f32.f16.f16.f32 "
        "{%0,%1,%2,%3}, {%4,%5,%6,%7}, {%8,%9}, {%0,%1,%2,%3};"
        : "+f"(d[0]), "+f"(d[1]), "+f"(d[2]), "+f"(d[3])
        : "r"(a[0]), "r"(a[1]), "r"(a[2]), "r"(a[3]), "r"(b[0]), "r"(b[1]));
}

// ---------------------------------------------------------------------------
// Prep: fp32 -> fp16 convert of x
// ---------------------------------------------------------------------------
__global__ void convert_x_kernel(const float* __restrict__ x,
                                 __half* __restrict__ o) {
    size_t i = ((size_t)blockIdx.x * 256 + threadIdx.x) * 4;
    float4 f = *reinterpret_cast<const float4*>(x + i);
    __half2 h0 = __floats2half2_rn(f.x, f.y);
    __half2 h1 = __floats2half2_rn(f.z, f.w);
    *reinterpret_cast<uint2*>(o + i) =
        make_uint2(*reinterpret_cast<uint32_t*>(&h0), *reinterpret_cast<uint32_t*>(&h1));
}

// ---------------------------------------------------------------------------
// Prep: per-v transpose [v][R][C] -> [v][C][R] + fp16 convert
// ---------------------------------------------------------------------------
__global__ void transpose_convert_kernel(const float* __restrict__ in,
                                         __half* __restrict__ o,
                                         int R, int C) {
    __shared__ float t[32][33];
    const int v = blockIdx.z;
    const float* src = in + (size_t)v * R * C;
    const size_t ob = (size_t)v * R * C;
    const int tx = threadIdx.x, ty = threadIdx.y;
    const int c = blockIdx.x * 32 + tx;
#pragma unroll
    for (int j = 0; j < 32; j += 8) {
        int r = blockIdx.y * 32 + ty + j;
        t[ty + j][tx] = src[(size_t)r * C + c];
    }
    __syncthreads();
    const int r2 = blockIdx.y * 32 + tx;  // output fast dim (R index)
#pragma unroll
    for (int j = 0; j < 32; j += 8) {
        int c2 = blockIdx.x * 32 + ty + j;  // output row (C index)
        o[ob + (size_t)c2 * R + r2] = __float2half_rn(t[tx][ty + j]);
    }
}

// ---------------------------------------------------------------------------
// Batched fp16 GEMM via mma.sync (fp32 accumulate):
//   D[128 x NT] = A[128 x K] * B[NT x K]^T  (per (m-block, v, n-block) CTA)
//   8 warps, warp grid WG_M x WG_N, warp tile (WM*16) x (WN*8)
//   Kc = 64 per chunk, 3-stage cp.async pipeline, SW128 swizzle, ldmatrix
//   (R4 structure exactly; loader uses precomputed offsets + advancing ptrs)
// ---------------------------------------------------------------------------
template <int NT, int WG_M, int WG_N, int WM, int WN, bool RELU>
__global__ void __launch_bounds__(256) gemm_kernel(
    const __half* __restrict__ A, long long aVStride,
    const __half* __restrict__ B,
    int K, int Ndim, int nPerV,
    const float* __restrict__ bias,
    __half* __restrict__ O,
    float* __restrict__ out)
{
    static_assert(WG_M * WG_N == 8, "8 warps");
    static_assert(WG_M * WM * 16 == 128, "M tile 128");
    static_assert(WG_N * WN * 8 == NT, "N tile");
    static_assert(WN % 2 == 0, "B ldmatrix pairs");

    extern __shared__ __align__(1024) char smem[];
    const uint32_t sb = smem_u32(smem);
    const int tid = threadIdx.x, wid = tid >> 5, lane = tid & 31;
    const int v  = blockIdx.y / nPerV, nb = blockIdx.y % nPerV;
    const int m0 = blockIdx.x * 128;
    const int n0 = nb * NT;
    const int NC = K >> 6;                 // K chunks of 64

    constexpr int A_SZ = 128 * 128;        // bytes per A tile per stage (16KB)
    constexpr int B_SZ = NT * 128;
    constexpr int STG  = A_SZ + B_SZ;
    const uint32_t st[3] = { sb, sb + STG, sb + 2 * STG };

    // ---- precomputed loader slices ----
    // A: 128 rows x 8 16B-units; 2 threads/row, 4 units each
    const int ar  = tid >> 1;
    const int au0 = (tid & 1) * 4;
    uint32_t aOff[4];
#pragma unroll
    for (int u = 0; u < 4; u++) aOff[u] = swz((uint32_t)(ar * 128 + (au0 + u) * 16));
    // B: NT rows x 8 units; BU = NT/32 units per thread
    constexpr int BU  = NT / 32;           // 4 (NT=128) or 2 (NT=64)
    constexpr int TPR = 8 / BU;            // threads per row
    const int br  = tid / TPR;
    const int bu0 = (tid % TPR) * BU;
    uint32_t bOff[BU];
#pragma unroll
    for (int u = 0; u < BU; u++) bOff[u] = swz((uint32_t)(br * 128 + (bu0 + u) * 16));

    const __half* aSrc = A + (size_t)v * aVStride + (size_t)(m0 + ar) * K + au0 * 8;
    const __half* bSrc = B + ((size_t)v * Ndim + n0 + br) * K + bu0 * 8;

    auto load_chunk = [&](int s) {
        const uint32_t aS = st[s], bS = st[s] + A_SZ;
#pragma unroll
        for (int u = 0; u < 4; u++) cp16(aS + aOff[u], aSrc + u * 8);
#pragma unroll
        for (int u = 0; u < BU; u++) cp16(bS + bOff[u], bSrc + u * 8);
        cp_commit();
        aSrc += 64;  // next K chunk
        bSrc += 64;
    };

    // warp tile origin
    const int wm = (wid / WG_N) * (WM * 16);
    const int wn = (wid % WG_N) * (WN * 8);

    float d[WM][WN][4];
#pragma unroll
    for (int i = 0; i < WM; i++)
#pragma unroll
        for (int j = 0; j < WN; j++)
#pragma unroll
            for (int q = 0; q < 4; q++) d[i][j][q] = 0.0f;

    load_chunk(0);
    load_chunk(1);

    // ldmatrix lane patterns
    const int aRow = (lane & 15);
    const int aKh  = (lane >> 4) * 8;
    const int bRow = (lane & 7) + (((lane >> 4) & 1) << 3);
    const int bKh  = ((lane >> 3) & 1) * 8;

    for (int kc = 0; kc < NC; kc++) {
        const int s = kc % 3;
        if (kc + 2 <= NC) { cp_wait<1>(); } else { cp_wait<0>(); }
        __syncthreads();
        if (kc + 2 < NC) load_chunk((kc + 2) % 3);

        const uint32_t aS = st[s], bS = st[s] + A_SZ;

#pragma unroll
        for (int ks = 0; ks < 4; ks++) {
            const int k0 = ks * 16;
            uint32_t af[WM][4], bf[WN][2];
#pragma unroll
            for (int i = 0; i < WM; i++) {
                uint32_t off = swz((uint32_t)((wm + aRow + i * 16) * 128 + (k0 + aKh) * 2));
                ldsm4(af[i][0], af[i][1], af[i][2], af[i][3], aS + off);
            }
#pragma unroll
            for (int j2 = 0; j2 < WN / 2; j2++) {
                uint32_t off = swz((uint32_t)((wn + bRow + j2 * 16) * 128 + (k0 + bKh) * 2));
                ldsm4(bf[2 * j2][0], bf[2 * j2][1], bf[2 * j2 + 1][0], bf[2 * j2 + 1][1], bS + off);
            }
#pragma unroll
            for (int i = 0; i < WM; i++)
#pragma unroll
                for (int j = 0; j < WN; j++) mma16816(d[i][j], af[i], bf[j]);
        }
    }

    // ---- epilogue (register fragments, canonical m16n8 D mapping) ----
    const int rBase = lane >> 2;         // 0..7
    const int cBase = (lane & 3) * 2;    // 0,2,4,6
#pragma unroll
    for (int j = 0; j < WN; j++) {
        const int n = n0 + wn + j * 8 + cBase;   // global n (even)
        float bv0 = 0.0f, bv1 = 0.0f;
        if (RELU) {
            bv0 = bias[(size_t)v * kH + n];
            bv1 = bias[(size_t)v * kH + n + 1];
        }
#pragma unroll
        for (int i = 0; i < WM; i++) {
#pragma unroll
            for (int half = 0; half < 2; half++) {
                const int m = m0 + wm + i * 16 + rBase + half * 8;
                float f0 = d[i][j][2 * half];
                float f1 = d[i][j][2 * half + 1];
                if (RELU) {
                    f0 = fmaxf(f0 + bv0, 0.0f);
                    f1 = fmaxf(f1 + bv1, 0.0f);
                    __half2 h2 = __floats2half2_rn(f0, f1);
                    size_t dst = ((size_t)v * kB + m) * kH + n;
                    *reinterpret_cast<uint32_t*>(O + dst) = *reinterpret_cast<uint32_t*>(&h2);
                } else {
                    size_t dst = (size_t)m * ((size_t)kV * kO) + (size_t)v * kO + n;
                    *reinterpret_cast<float2*>(out + dst) = make_float2(f0, f1);
                }
            }
        }
    }
}

// ---------------------------------------------------------------------------
// Launch
// ---------------------------------------------------------------------------
extern "C" void kernel_launch(void* const* d_in, const int* in_sizes, int n_in,
                              void* d_out, int out_size) {
    const float* x  = (const float*)d_in[0];
    const float* W1 = (const float*)d_in[1];
    const float* b1 = (const float*)d_in[2];
    const float* W2 = (const float*)d_in[3];
    const float* b2 = (const float*)d_in[4];
    const float* W3 = (const float*)d_in[5];
    float* out = (float*)d_out;

    void *pX, *pW1, *pW2, *pW3, *pH1, *pH2;
    cudaGetSymbolAddress(&pX,  g_X);
    cudaGetSymbolAddress(&pW1, g_W1);
    cudaGetSymbolAddress(&pW2, g_W2);
    cudaGetSymbolAddress(&pW3, g_W3);
    cudaGetSymbolAddress(&pH1, g_H1);
    cudaGetSymbolAddress(&pH2, g_H2);

    // smem: 3 stages * (16KB A + NT*128 B)
    constexpr int SMEM_BIG = 3 * (128 * 128 + 128 * 128);  // NT=128 -> 96KB
    constexpr int SMEM_SM  = 3 * (128 * 128 + 64 * 128);   // NT=64  -> 72KB
    cudaFuncSetAttribute((const void*)gemm_kernel<128, 2, 4, 4, 4, true>,
                         cudaFuncAttributeMaxDynamicSharedMemorySize, SMEM_BIG);
    cudaFuncSetAttribute((const void*)gemm_kernel<64, 4, 2, 2, 4, false>,
                         cudaFuncAttributeMaxDynamicSharedMemorySize, SMEM_SM);

    // prep: convert x, transpose+convert weights
    convert_x_kernel<<<(kB * kIN) / 1024, 256>>>(x, (__half*)pX);
    dim3 tb(32, 8);
    transpose_convert_kernel<<<dim3(kH / 32, kIN / 32, kV), tb>>>(W1, (__half*)pW1, kIN, kH);
    transpose_convert_kernel<<<dim3(kH / 32, kH / 32, kV), tb>>>(W2, (__half*)pW2, kH, kH);
    transpose_convert_kernel<<<dim3(kO / 32, kH / 32, kV), tb>>>(W3, (__half*)pW3, kH, kO);

    // layer 1: [4096,1024] x [48,512,1024]^T -> H1
    gemm_kernel<128, 2, 4, 4, 4, true><<<dim3(kB / 128, kV * (kH / 128)), 256, SMEM_BIG>>>(
        (const __half*)pX, 0LL, (const __half*)pW1,
        kIN, kH, kH / 128, b1, (__half*)pH1, nullptr);

    // layer 2: H1 x [48,512,512]^T -> H2
    gemm_kernel<128, 2, 4, 4, 4, true><<<dim3(kB / 128, kV * (kH / 128)), 256, SMEM_BIG>>>(
        (const __half*)pH1, (long long)kB * kH, (const __half*)pW2,
        kH, kH, kH / 128, b2, (__half*)pH2, nullptr);

    // layer 3: H2 x [48,64,512]^T -> out (fp32, no bias/relu)
    gemm_kernel<64, 4, 2, 2, 4, false><<<dim3(kB / 128, kV), 256, SMEM_SM>>>(
        (const __half*)pH2, (long long)kB * kH, (const __half*)pW3,
        kH, kO, 1, nullptr, nullptr, out);
}

// round 16
// speedup vs baseline: 1.7894x; 1.0872x over previous
#include <cuda_runtime.h>
#include <cuda_fp16.h>
#include <cstdint>
#include <cstddef>

// ---------------------------------------------------------------------------
// Problem dims
// ---------------------------------------------------------------------------
constexpr int kB  = 4096;   // batch
constexpr int kIN = 1024;   // input dim
constexpr int kV  = 48;     // vocab (num MLPs)
constexpr int kH  = 512;    // hidden
constexpr int kO  = 64;     // out per MLP

// ---------------------------------------------------------------------------
// Device scratch: fp16 operands + intermediates
// ---------------------------------------------------------------------------
__device__ __align__(1024) __half g_X  [(size_t)kB * kIN];
__device__ __align__(1024) __half g_W1 [(size_t)kV * kH * kIN];  // [v][h][i]
__device__ __align__(1024) __half g_W2 [(size_t)kV * kH * kH];   // [v][k][h]
__device__ __align__(1024) __half g_W3 [(size_t)kV * kO * kH];   // [v][o][k]
__device__ __align__(1024) __half g_H1 [(size_t)kV * kB * kH];   // [v][m][h]
__device__ __align__(1024) __half g_H2 [(size_t)kV * kB * kH];

// ---------------------------------------------------------------------------
// PTX helpers — baseline (non-'a') PTX only: cp.async / ldmatrix / mma.sync
// ---------------------------------------------------------------------------
#define DINLINE __device__ __forceinline__

DINLINE uint32_t smem_u32(const void* p) {
    uint32_t a;
    asm("{ .reg .u64 t; cvta.to.shared.u64 t, %1; cvt.u32.u64 %0, t; }" : "=r"(a) : "l"(p));
    return a;
}
DINLINE uint32_t swz(uint32_t o) { return o ^ ((o >> 3) & 0x70); }

DINLINE void cp16(uint32_t dst, const void* src) {
    asm volatile("cp.async.cg.shared.global [%0], [%1], 16;" :: "r"(dst), "l"(src));
}
DINLINE void cp_commit() { asm volatile("cp.async.commit_group;" ::: "memory"); }
template <int N> DINLINE void cp_wait() {
    asm volatile("cp.async.wait_group %0;" :: "n"(N) : "memory");
}

DINLINE void ldsm4(uint32_t& r0, uint32_t& r1, uint32_t& r2, uint32_t& r3, uint32_t a) {
    asm volatile("ldmatrix.sync.aligned.m8n8.x4.shared.b16 {%0,%1,%2,%3}, [%4];"
                 : "=r"(r0), "=r"(r1), "=r"(r2), "=r"(r3) : "r"(a));
}

DINLINE void mma16816(float* d, const uint32_t* a, const uint32_t* b) {
    asm volatile(
        "mma.sync.aligned.m16n8k16.row.col.f32.f16.f16.f32 "
        "{%0,%1,%2,%3}, {%4,%5,%6,%7}, {%8,%9}, {%0,%1,%2,%3};"
        : "+f"(d[0]), "+f"(d[1]), "+f"(d[2]), "+f"(d[3])
        : "r"(a[0]), "r"(a[1]), "r"(a[2]), "r"(a[3]), "r"(b[0]), "r"(b[1]));
}

// ---------------------------------------------------------------------------
// Prep: fp32 -> fp16 convert of x
// ---------------------------------------------------------------------------
__global__ void convert_x_kernel(const float* __restrict__ x,
                                 __half* __restrict__ o) {
    size_t i = ((size_t)blockIdx.x * 256 + threadIdx.x) * 4;
    float4 f = *reinterpret_cast<const float4*>(x + i);
    __half2 h0 = __floats2half2_rn(f.x, f.y);
    __half2 h1 = __floats2half2_rn(f.z, f.w);
    *reinterpret_cast<uint2*>(o + i) =
        make_uint2(*reinterpret_cast<uint32_t*>(&h0), *reinterpret_cast<uint32_t*>(&h1));
}

// ---------------------------------------------------------------------------
// Prep: per-v transpose [v][R][C] -> [v][C][R] + fp16 convert
// ---------------------------------------------------------------------------
__global__ void transpose_convert_kernel(const float* __restrict__ in,
                                         __half* __restrict__ o,
                                         int R, int C) {
    __shared__ float t[32][33];
    const int v = blockIdx.z;
    const float* src = in + (size_t)v * R * C;
    const size_t ob = (size_t)v * R * C;
    const int tx = threadIdx.x, ty = threadIdx.y;
    const int c = blockIdx.x * 32 + tx;
#pragma unroll
    for (int j = 0; j < 32; j += 8) {
        int r = blockIdx.y * 32 + ty + j;
        t[ty + j][tx] = src[(size_t)r * C + c];
    }
    __syncthreads();
    const int r2 = blockIdx.y * 32 + tx;  // output fast dim (R index)
#pragma unroll
    for (int j = 0; j < 32; j += 8) {
        int c2 = blockIdx.x * 32 + ty + j;  // output row (C index)
        o[ob + (size_t)c2 * R + r2] = __float2half_rn(t[tx][ty + j]);
    }
}

// ---------------------------------------------------------------------------
// Batched fp16 GEMM via mma.sync (fp32 accumulate):
//   D[128 x NT] = A[128 x K] * B[NT x K]^T  (per (m-block, v, n-block) CTA)
//   8 warps, warp grid WG_M x WG_N, warp tile (WM*16) x (WN*8)
//   Kc = 128 per chunk, stored as TWO 64-K sub-tiles each with the R4
//   128B-row SW128 layout (ldmatrix offset formulas unchanged).
//   3-stage cp.async pipeline; loader recomputes indices per chunk (no
//   long-lived address registers — that spills, measured R15).
// ---------------------------------------------------------------------------
template <int NT, int WG_M, int WG_N, int WM, int WN, bool RELU>
__global__ void __launch_bounds__(256) gemm_kernel(
    const __half* __restrict__ A, long long aVStride,
    const __half* __restrict__ B,
    int K, int Ndim, int nPerV,
    const float* __restrict__ bias,
    __half* __restrict__ O,
    float* __restrict__ out)
{
    static_assert(WG_M * WG_N == 8, "8 warps");
    static_assert(WG_M * WM * 16 == 128, "M tile 128");
    static_assert(WG_N * WN * 8 == NT, "N tile");
    static_assert(WN % 2 == 0, "B ldmatrix pairs");

    extern __shared__ __align__(1024) char smem[];
    const uint32_t sb = smem_u32(smem);
    const int tid = threadIdx.x, wid = tid >> 5, lane = tid & 31;
    const int v  = blockIdx.y / nPerV, nb = blockIdx.y % nPerV;
    const int m0 = blockIdx.x * 128;
    const int n0 = nb * NT;
    const int NC = K >> 7;                 // K chunks of 128

    constexpr int A_HALF = 128 * 128;      // one 64-K sub-tile of A (16KB)
    constexpr int B_HALF = NT * 128;       // one 64-K sub-tile of B
    constexpr int A_SZ = 2 * A_HALF;       // A per stage (32KB)
    constexpr int B_SZ = 2 * B_HALF;
    constexpr int STG  = A_SZ + B_SZ;
    const uint32_t st[3] = { sb, sb + STG, sb + 2 * STG };

    const __half* A_ = A + (size_t)v * aVStride;
    const __half* B_ = B + ((size_t)v * Ndim + n0) * K;

    // ---- chunk loader: Kc=128 cols starting at kk into stage s ----
    // unit u in [0,16): u<8 -> sub-tile 0, u>=8 -> sub-tile 1 (+16KB / +B_HALF)
    auto load_chunk = [&](int s, int kk) {
        const uint32_t aS = st[s], bS = st[s] + A_SZ;
        for (int idx = tid; idx < 128 * 16; idx += 256) {
            int r = idx >> 4, u = idx & 15;
            uint32_t so = (uint32_t)((u >> 3) * A_HALF) + swz((uint32_t)(r * 128 + (u & 7) * 16));
            cp16(aS + so, A_ + (size_t)(m0 + r) * K + kk + u * 8);
        }
        for (int idx = tid; idx < NT * 16; idx += 256) {
            int r = idx >> 4, u = idx & 15;
            uint32_t so = (uint32_t)((u >> 3) * B_HALF) + swz((uint32_t)(r * 128 + (u & 7) * 16));
            cp16(bS + so, B_ + (size_t)r * K + kk + u * 8);
        }
        cp_commit();
    };

    // warp tile origin
    const int wm = (wid / WG_N) * (WM * 16);
    const int wn = (wid % WG_N) * (WN * 8);

    float d[WM][WN][4];
#pragma unroll
    for (int i = 0; i < WM; i++)
#pragma unroll
        for (int j = 0; j < WN; j++)
#pragma unroll
            for (int q = 0; q < 4; q++) d[i][j][q] = 0.0f;

    load_chunk(0, 0);
    load_chunk(1, 128);

    // ldmatrix lane patterns
    const int aRow = (lane & 15);
    const int aKh  = (lane >> 4) * 8;
    const int bRow = (lane & 7) + (((lane >> 4) & 1) << 3);
    const int bKh  = ((lane >> 3) & 1) * 8;

    for (int kc = 0; kc < NC; kc++) {
        const int s = kc % 3;
        if (kc + 2 <= NC) { cp_wait<1>(); } else { cp_wait<0>(); }
        __syncthreads();
        if (kc + 2 < NC) load_chunk((kc + 2) % 3, (kc + 2) * 128);

        const uint32_t aS0 = st[s], bS0 = st[s] + A_SZ;

#pragma unroll
        for (int ks = 0; ks < 8; ks++) {
            const uint32_t aS = aS0 + (ks >= 4 ? A_HALF : 0);
            const uint32_t bS = bS0 + (ks >= 4 ? B_HALF : 0);
            const int k0 = (ks & 3) * 16;
            uint32_t af[WM][4], bf[WN][2];
#pragma unroll
            for (int i = 0; i < WM; i++) {
                uint32_t off = swz((uint32_t)((wm + aRow + i * 16) * 128 + (k0 + aKh) * 2));
                ldsm4(af[i][0], af[i][1], af[i][2], af[i][3], aS + off);
            }
#pragma unroll
            for (int j2 = 0; j2 < WN / 2; j2++) {
                uint32_t off = swz((uint32_t)((wn + bRow + j2 * 16) * 128 + (k0 + bKh) * 2));
                ldsm4(bf[2 * j2][0], bf[2 * j2][1], bf[2 * j2 + 1][0], bf[2 * j2 + 1][1], bS + off);
            }
#pragma unroll
            for (int i = 0; i < WM; i++)
#pragma unroll
                for (int j = 0; j < WN; j++) mma16816(d[i][j], af[i], bf[j]);
        }
    }

    // ---- epilogue (register fragments, canonical m16n8 D mapping) ----
    const int rBase = lane >> 2;         // 0..7
    const int cBase = (lane & 3) * 2;    // 0,2,4,6
#pragma unroll
    for (int j = 0; j < WN; j++) {
        const int n = n0 + wn + j * 8 + cBase;   // global n (even)
        float bv0 = 0.0f, bv1 = 0.0f;
        if (RELU) {
            bv0 = bias[(size_t)v * kH + n];
            bv1 = bias[(size_t)v * kH + n + 1];
        }
#pragma unroll
        for (int i = 0; i < WM; i++) {
#pragma unroll
            for (int half = 0; half < 2; half++) {
                const int m = m0 + wm + i * 16 + rBase + half * 8;
                float f0 = d[i][j][2 * half];
                float f1 = d[i][j][2 * half + 1];
                if (RELU) {
                    f0 = fmaxf(f0 + bv0, 0.0f);
                    f1 = fmaxf(f1 + bv1, 0.0f);
                    __half2 h2 = __floats2half2_rn(f0, f1);
                    size_t dst = ((size_t)v * kB + m) * kH + n;
                    *reinterpret_cast<uint32_t*>(O + dst) = *reinterpret_cast<uint32_t*>(&h2);
                } else {
                    size_t dst = (size_t)m * ((size_t)kV * kO) + (size_t)v * kO + n;
                    *reinterpret_cast<float2*>(out + dst) = make_float2(f0, f1);
                }
            }
        }
    }
}

// ---------------------------------------------------------------------------
// Launch
// ---------------------------------------------------------------------------
extern "C" void kernel_launch(void* const* d_in, const int* in_sizes, int n_in,
                              void* d_out, int out_size) {
    const float* x  = (const float*)d_in[0];
    const float* W1 = (const float*)d_in[1];
    const float* b1 = (const float*)d_in[2];
    const float* W2 = (const float*)d_in[3];
    const float* b2 = (const float*)d_in[4];
    const float* W3 = (const float*)d_in[5];
    float* out = (float*)d_out;

    void *pX, *pW1, *pW2, *pW3, *pH1, *pH2;
    cudaGetSymbolAddress(&pX,  g_X);
    cudaGetSymbolAddress(&pW1, g_W1);
    cudaGetSymbolAddress(&pW2, g_W2);
    cudaGetSymbolAddress(&pW3, g_W3);
    cudaGetSymbolAddress(&pH1, g_H1);
    cudaGetSymbolAddress(&pH2, g_H2);

    // smem: 3 stages * (32KB A + 2*NT*128 B)
    constexpr int SMEM_BIG = 3 * (2 * 128 * 128 + 2 * 128 * 128);  // NT=128 -> 192KB
    constexpr int SMEM_SM  = 3 * (2 * 128 * 128 + 2 * 64 * 128);   // NT=64  -> 144KB
    cudaFuncSetAttribute((const void*)gemm_kernel<128, 2, 4, 4, 4, true>,
                         cudaFuncAttributeMaxDynamicSharedMemorySize, SMEM_BIG);
    cudaFuncSetAttribute((const void*)gemm_kernel<64, 4, 2, 2, 4, false>,
                         cudaFuncAttributeMaxDynamicSharedMemorySize, SMEM_SM);

    // prep: convert x, transpose+convert weights
    convert_x_kernel<<<(kB * kIN) / 1024, 256>>>(x, (__half*)pX);
    dim3 tb(32, 8);
    transpose_convert_kernel<<<dim3(kH / 32, kIN / 32, kV), tb>>>(W1, (__half*)pW1, kIN, kH);
    transpose_convert_kernel<<<dim3(kH / 32, kH / 32, kV), tb>>>(W2, (__half*)pW2, kH, kH);
    transpose_convert_kernel<<<dim3(kO / 32, kH / 32, kV), tb>>>(W3, (__half*)pW3, kH, kO);

    // layer 1: [4096,1024] x [48,512,1024]^T -> H1
    gemm_kernel<128, 2, 4, 4, 4, true><<<dim3(kB / 128, kV * (kH / 128)), 256, SMEM_BIG>>>(
        (const __half*)pX, 0LL, (const __half*)pW1,
        kIN, kH, kH / 128, b1, (__half*)pH1, nullptr);

    // layer 2: H1 x [48,512,512]^T -> H2
    gemm_kernel<128, 2, 4, 4, 4, true><<<dim3(kB / 128, kV * (kH / 128)), 256, SMEM_BIG>>>(
        (const __half*)pH1, (long long)kB * kH, (const __half*)pW2,
        kH, kH, kH / 128, b2, (__half*)pH2, nullptr);

    // layer 3: H2 x [48,64,512]^T -> out (fp32, no bias/relu)
    gemm_kernel<64, 4, 2, 2, 4, false><<<dim3(kB / 128, kV), 256, SMEM_SM>>>(
        (const __half*)pH2, (long long)kB * kH, (const __half*)pW3,
        kH, kO, 1, nullptr, nullptr, out);
}

// round 17
// speedup vs baseline: 1.8664x; 1.0430x over previous
#include <cuda_runtime.h>
#include <cuda_fp16.h>
#include <cstdint>
#include <cstddef>

// ---------------------------------------------------------------------------
// Problem dims
// ---------------------------------------------------------------------------
constexpr int kB  = 4096;   // batch
constexpr int kIN = 1024;   // input dim
constexpr int kV  = 48;     // vocab (num MLPs)
constexpr int kH  = 512;    // hidden
constexpr int kO  = 64;     // out per MLP

// ---------------------------------------------------------------------------
// Device scratch: fp16 operands + intermediates
// ---------------------------------------------------------------------------
__device__ __align__(1024) __half g_X  [(size_t)kB * kIN];
__device__ __align__(1024) __half g_W1 [(size_t)kV * kH * kIN];  // [v][h][i]
__device__ __align__(1024) __half g_W2 [(size_t)kV * kH * kH];   // [v][k][h]
__device__ __align__(1024) __half g_W3 [(size_t)kV * kO * kH];   // [v][o][k]
__device__ __align__(1024) __half g_H1 [(size_t)kV * kB * kH];   // [v][m][h]
__device__ __align__(1024) __half g_H2 [(size_t)kV * kB * kH];

// ---------------------------------------------------------------------------
// PTX helpers — baseline (non-'a') PTX only: cp.async / ldmatrix / mma.sync
// ---------------------------------------------------------------------------
#define DINLINE __device__ __forceinline__

DINLINE uint32_t smem_u32(const void* p) {
    uint32_t a;
    asm("{ .reg .u64 t; cvta.to.shared.u64 t, %1; cvt.u32.u64 %0, t; }" : "=r"(a) : "l"(p));
    return a;
}
DINLINE uint32_t swz(uint32_t o) { return o ^ ((o >> 3) & 0x70); }

DINLINE void cp16(uint32_t dst, const void* src) {
    asm volatile("cp.async.cg.shared.global [%0], [%1], 16;" :: "r"(dst), "l"(src));
}
DINLINE void cp_commit() { asm volatile("cp.async.commit_group;" ::: "memory"); }
template <int N> DINLINE void cp_wait() {
    asm volatile("cp.async.wait_group %0;" :: "n"(N) : "memory");
}

DINLINE void ldsm4(uint32_t& r0, uint32_t& r1, uint32_t& r2, uint32_t& r3, uint32_t a) {
    asm volatile("ldmatrix.sync.aligned.m8n8.x4.shared.b16 {%0,%1,%2,%3}, [%4];"
                 : "=r"(r0), "=r"(r1), "=r"(r2), "=r"(r3) : "r"(a));
}

DINLINE void mma16816(float* d, const uint32_t* a, const uint32_t* b) {
    asm volatile(
        "mma.sync.aligned.m16n8k16.row.col.f32.f16.f16.f32 "
        "{%0,%1,%2,%3}, {%4,%5,%6,%7}, {%8,%9}, {%0,%1,%2,%3};"
        : "+f"(d[0]), "+f"(d[1]), "+f"(d[2]), "+f"(d[3])
        : "r"(a[0]), "r"(a[1]), "r"(a[2]), "r"(a[3]), "r"(b[0]), "r"(b[1]));
}

// ---------------------------------------------------------------------------
// Prep: fp32 -> fp16 convert of x
// ---------------------------------------------------------------------------
__global__ void convert_x_kernel(const float* __restrict__ x,
                                 __half* __restrict__ o) {
    size_t i = ((size_t)blockIdx.x * 256 + threadIdx.x) * 4;
    float4 f = *reinterpret_cast<const float4*>(x + i);
    __half2 h0 = __floats2half2_rn(f.x, f.y);
    __half2 h1 = __floats2half2_rn(f.z, f.w);
    *reinterpret_cast<uint2*>(o + i) =
        make_uint2(*reinterpret_cast<uint32_t*>(&h0), *reinterpret_cast<uint32_t*>(&h1));
}

// ---------------------------------------------------------------------------
// Prep: per-v transpose [v][R][C] -> [v][C][R] + fp16 convert
// ---------------------------------------------------------------------------
__global__ void transpose_convert_kernel(const float* __restrict__ in,
                                         __half* __restrict__ o,
                                         int R, int C) {
    __shared__ float t[32][33];
    const int v = blockIdx.z;
    const float* src = in + (size_t)v * R * C;
    const size_t ob = (size_t)v * R * C;
    const int tx = threadIdx.x, ty = threadIdx.y;
    const int c = blockIdx.x * 32 + tx;
#pragma unroll
    for (int j = 0; j < 32; j += 8) {
        int r = blockIdx.y * 32 + ty + j;
        t[ty + j][tx] = src[(size_t)r * C + c];
    }
    __syncthreads();
    const int r2 = blockIdx.y * 32 + tx;  // output fast dim (R index)
#pragma unroll
    for (int j = 0; j < 32; j += 8) {
        int c2 = blockIdx.x * 32 + ty + j;  // output row (C index)
        o[ob + (size_t)c2 * R + r2] = __float2half_rn(t[tx][ty + j]);
    }
}

// ---------------------------------------------------------------------------
// Batched fp16 GEMM via mma.sync (fp32 accumulate):
//   D[128 x 64] = A[128 x K] * B[64 x K]^T  (per (m-block, v, n-block) CTA)
//   128 threads / 4 warps, warp grid 2x2, warp tile 64x32 (WM=4, WN=4 — the
//   proven no-spill register structure from the 979.7us kernel).
//   Kc = 64 per chunk, 3-stage cp.async pipeline, SW128 swizzle, ldmatrix.
//   Small CTA -> ~21K regs & 72KB smem per CTA -> 3 CTAs/SM (12 warps).
// ---------------------------------------------------------------------------
template <bool RELU>
__global__ void __launch_bounds__(128) gemm_kernel(
    const __half* __restrict__ A, long long aVStride,
    const __half* __restrict__ B,
    int K, int Ndim, int nPerV,
    const float* __restrict__ bias,
    __half* __restrict__ O,
    float* __restrict__ out)
{
    constexpr int NT = 64;                 // N tile
    constexpr int WM = 4, WN = 4;          // warp tile 64x32
    constexpr int WG_N = 2;                // warp grid 2x2

    extern __shared__ __align__(1024) char smem[];
    const uint32_t sb = smem_u32(smem);
    const int tid = threadIdx.x, wid = tid >> 5, lane = tid & 31;
    const int v  = blockIdx.y / nPerV, nb = blockIdx.y % nPerV;
    const int m0 = blockIdx.x * 128;
    const int n0 = nb * NT;
    const int NC = K >> 6;                 // K chunks of 64

    constexpr int A_SZ = 128 * 128;        // A tile per stage (16KB)
    constexpr int B_SZ = NT * 128;         // B tile per stage (8KB)
    constexpr int STG  = A_SZ + B_SZ;
    const uint32_t st[3] = { sb, sb + STG, sb + 2 * STG };

    const __half* A_ = A + (size_t)v * aVStride;
    const __half* B_ = B + ((size_t)v * Ndim + n0) * K;

    // ---- chunk loader: Kc=64 cols starting at kk into stage s ----
    auto load_chunk = [&](int s, int kk) {
        const uint32_t aS = st[s], bS = st[s] + A_SZ;
        for (int idx = tid; idx < 128 * 8; idx += 128) {
            int r = idx >> 3, u = idx & 7;
            uint32_t so = swz((uint32_t)(r * 128 + u * 16));
            cp16(aS + so, A_ + (size_t)(m0 + r) * K + kk + u * 8);
        }
        for (int idx = tid; idx < NT * 8; idx += 128) {
            int r = idx >> 3, u = idx & 7;
            uint32_t so = swz((uint32_t)(r * 128 + u * 16));
            cp16(bS + so, B_ + (size_t)r * K + kk + u * 8);
        }
        cp_commit();
    };

    // warp tile origin (2x2 warp grid)
    const int wm = (wid / WG_N) * (WM * 16);
    const int wn = (wid % WG_N) * (WN * 8);

    float d[WM][WN][4];
#pragma unroll
    for (int i = 0; i < WM; i++)
#pragma unroll
        for (int j = 0; j < WN; j++)
#pragma unroll
            for (int q = 0; q < 4; q++) d[i][j][q] = 0.0f;

    load_chunk(0, 0);
    load_chunk(1, 64);

    // ldmatrix lane patterns
    const int aRow = (lane & 15);
    const int aKh  = (lane >> 4) * 8;
    const int bRow = (lane & 7) + (((lane >> 4) & 1) << 3);
    const int bKh  = ((lane >> 3) & 1) * 8;

    for (int kc = 0; kc < NC; kc++) {
        const int s = kc % 3;
        if (kc + 2 <= NC) { cp_wait<1>(); } else { cp_wait<0>(); }
        __syncthreads();
        if (kc + 2 < NC) load_chunk((kc + 2) % 3, (kc + 2) * 64);

        const uint32_t aS = st[s], bS = st[s] + A_SZ;

#pragma unroll
        for (int ks = 0; ks < 4; ks++) {
            const int k0 = ks * 16;
            uint32_t af[WM][4], bf[WN][2];
#pragma unroll
            for (int i = 0; i < WM; i++) {
                uint32_t off = swz((uint32_t)((wm + aRow + i * 16) * 128 + (k0 + aKh) * 2));
                ldsm4(af[i][0], af[i][1], af[i][2], af[i][3], aS + off);
            }
#pragma unroll
            for (int j2 = 0; j2 < WN / 2; j2++) {
                uint32_t off = swz((uint32_t)((wn + bRow + j2 * 16) * 128 + (k0 + bKh) * 2));
                ldsm4(bf[2 * j2][0], bf[2 * j2][1], bf[2 * j2 + 1][0], bf[2 * j2 + 1][1], bS + off);
            }
#pragma unroll
            for (int i = 0; i < WM; i++)
#pragma unroll
                for (int j = 0; j < WN; j++) mma16816(d[i][j], af[i], bf[j]);
        }
    }

    // ---- epilogue (register fragments, canonical m16n8 D mapping) ----
    const int rBase = lane >> 2;         // 0..7
    const int cBase = (lane & 3) * 2;    // 0,2,4,6
#pragma unroll
    for (int j = 0; j < WN; j++) {
        const int n = n0 + wn + j * 8 + cBase;   // global n (even)
        float bv0 = 0.0f, bv1 = 0.0f;
        if (RELU) {
            bv0 = bias[(size_t)v * kH + n];
            bv1 = bias[(size_t)v * kH + n + 1];
        }
#pragma unroll
        for (int i = 0; i < WM; i++) {
#pragma unroll
            for (int half = 0; half < 2; half++) {
                const int m = m0 + wm + i * 16 + rBase + half * 8;
                float f0 = d[i][j][2 * half];
                float f1 = d[i][j][2 * half + 1];
                if (RELU) {
                    f0 = fmaxf(f0 + bv0, 0.0f);
                    f1 = fmaxf(f1 + bv1, 0.0f);
                    __half2 h2 = __floats2half2_rn(f0, f1);
                    size_t dst = ((size_t)v * kB + m) * kH + n;
                    *reinterpret_cast<uint32_t*>(O + dst) = *reinterpret_cast<uint32_t*>(&h2);
                } else {
                    size_t dst = (size_t)m * ((size_t)kV * kO) + (size_t)v * kO + n;
                    *reinterpret_cast<float2*>(out + dst) = make_float2(f0, f1);
                }
            }
        }
    }
}

// ---------------------------------------------------------------------------
// Launch
// ---------------------------------------------------------------------------
extern "C" void kernel_launch(void* const* d_in, const int* in_sizes, int n_in,
                              void* d_out, int out_size) {
    const float* x  = (const float*)d_in[0];
    const float* W1 = (const float*)d_in[1];
    const float* b1 = (const float*)d_in[2];
    const float* W2 = (const float*)d_in[3];
    const float* b2 = (const float*)d_in[4];
    const float* W3 = (const float*)d_in[5];
    float* out = (float*)d_out;

    void *pX, *pW1, *pW2, *pW3, *pH1, *pH2;
    cudaGetSymbolAddress(&pX,  g_X);
    cudaGetSymbolAddress(&pW1, g_W1);
    cudaGetSymbolAddress(&pW2, g_W2);
    cudaGetSymbolAddress(&pW3, g_W3);
    cudaGetSymbolAddress(&pH1, g_H1);
    cudaGetSymbolAddress(&pH2, g_H2);

    // smem: 3 stages * (16KB A + 8KB B) = 72KB per CTA
    constexpr int SMEM = 3 * (128 * 128 + 64 * 128);
    cudaFuncSetAttribute((const void*)gemm_kernel<true>,
                         cudaFuncAttributeMaxDynamicSharedMemorySize, SMEM);
    cudaFuncSetAttribute((const void*)gemm_kernel<false>,
                         cudaFuncAttributeMaxDynamicSharedMemorySize, SMEM);

    // prep: convert x, transpose+convert weights
    convert_x_kernel<<<(kB * kIN) / 1024, 256>>>(x, (__half*)pX);
    dim3 tb(32, 8);
    transpose_convert_kernel<<<dim3(kH / 32, kIN / 32, kV), tb>>>(W1, (__half*)pW1, kIN, kH);
    transpose_convert_kernel<<<dim3(kH / 32, kH / 32, kV), tb>>>(W2, (__half*)pW2, kH, kH);
    transpose_convert_kernel<<<dim3(kO / 32, kH / 32, kV), tb>>>(W3, (__half*)pW3, kH, kO);

    // layer 1: [4096,1024] x [48,512,1024]^T -> H1   (8 n-blocks of 64 per v)
    gemm_kernel<true><<<dim3(kB / 128, kV * (kH / 64)), 128, SMEM>>>(
        (const __half*)pX, 0LL, (const __half*)pW1,
        kIN, kH, kH / 64, b1, (__half*)pH1, nullptr);

    // layer 2: H1 x [48,512,512]^T -> H2
    gemm_kernel<true><<<dim3(kB / 128, kV * (kH / 64)), 128, SMEM>>>(
        (const __half*)pH1, (long long)kB * kH, (const __half*)pW2,
        kH, kH, kH / 64, b2, (__half*)pH2, nullptr);

    // layer 3: H2 x [48,64,512]^T -> out (fp32, no bias/relu)
    gemm_kernel<false><<<dim3(kB / 128, kV), 128, SMEM>>>(
        (const __half*)pH2, (long long)kB * kH, (const __half*)pW3,
        kH, kO, 1, nullptr, nullptr, out);
}